// round 12
// baseline (speedup 1.0000x reference)
#include <cuda_runtime.h>
#include <cuda_bf16.h>
#include <stdint.h>

#define P_PTS   10000
#define NPTS    100
#define MAXB    4096

typedef unsigned long long ull;

// ------------------------------ scratch ------------------------------------
__device__ float g_phi [MAXB * 300];   // phi row-major [b][300]
__device__ float g_W1t [300 * 128];    // W1 transposed [k][c]
__device__ float g_Wct [256 * 256];    // [W3|W4] transposed [k][j]
__device__ float g_b34 [256];          // b3 + b4

// ------------------------------ f32x2 helpers -------------------------------
union F4U2 { float4 f4; ull u2[2]; float f[4]; };

__device__ __forceinline__ ull dup2(float a) {
    ull r; asm("mov.b64 %0, {%1, %1};" : "=l"(r) : "f"(a)); return r;
}
__device__ __forceinline__ void ffma2(ull& acc, ull a, ull b) {
    asm("fma.rn.f32x2 %0, %1, %2, %3;" : "=l"(acc) : "l"(a), "l"(b), "l"(acc));
}
__device__ __forceinline__ float2 unpack2(ull v) {
    float2 f; asm("mov.b64 {%0, %1}, %2;" : "=f"(f.x), "=f"(f.y) : "l"(v)); return f;
}

// ------------------------------ foveate (+ folded prep) ---------------------
// R11-proven: CTA-per-batch, 512 threads, 2048-pt float4 chunks, ballot-based
// ordered compaction, shfl cross-warp prefix, ONE sync per chunk, early exit.
__global__ void __launch_bounds__(512) foveate_kernel(
        const float* __restrict__ x,  const float* __restrict__ lt,
        const float* __restrict__ W1, const float* __restrict__ W3,
        const float* __restrict__ W4, const float* __restrict__ b3,
        const float* __restrict__ b4) {
    __shared__ float s0[NPTS], s1[NPTS], s2[NPTS];
    __shared__ int warp_cnt[2][16];

    int b = blockIdx.x;
    int tid = threadIdx.x, lane = tid & 31, wid = tid >> 5;

    // folded prep (independent; consumed by the MLP kernel)
    {
        int g = b * 512 + tid;
        if (g < 300 * 128) {
            int k = g / 128, c = g - k * 128;
            g_W1t[g] = W1[c * 300 + k];
        }
        if (g < 256 * 256) {
            int k = g >> 8, j = g & 255;
            g_Wct[g] = (k < 128) ? W3[j * 128 + k] : W4[j * 128 + (k - 128)];
        }
        if (g < 256) g_b34[g] = b3[g] + b4[g];
    }

    const float* xb = x + (size_t)b * 3 * P_PTS;
    float l0 = lt[b * 3 + 0], l1 = lt[b * 3 + 1], l2 = lt[b * 3 + 2];
    float lo0 = l0 - 0.25f, hi0 = l0 + 0.25f;
    float lo1 = l1 - 0.25f, hi1 = l1 + 0.25f;
    float lo2 = l2 - 0.25f, hi2 = l2 + 0.25f;
    unsigned ltm = (1u << lane) - 1u;

    int run = 0, buf = 0;
    for (int base = 0; base < P_PTS; base += 2048) {
        int p0 = base + tid * 4;
        float v0[4], v1[4], v2[4];
        unsigned m = 0;
        if (p0 < P_PTS) {  // P divisible by 4 -> float4 fully in or out
            float4 f0 = *(const float4*)(xb + p0);
            float4 f1 = *(const float4*)(xb + P_PTS + p0);
            float4 f2 = *(const float4*)(xb + 2 * P_PTS + p0);
            v0[0]=f0.x; v0[1]=f0.y; v0[2]=f0.z; v0[3]=f0.w;
            v1[0]=f1.x; v1[1]=f1.y; v1[2]=f1.z; v1[3]=f1.w;
            v2[0]=f2.x; v2[1]=f2.y; v2[2]=f2.z; v2[3]=f2.w;
#pragma unroll
            for (int i = 0; i < 4; i++) {
                bool in = (v0[i] >= lo0) && (v0[i] <= hi0) &&
                          (v1[i] >= lo1) && (v1[i] <= hi1) &&
                          (v2[i] >= lo2) && (v2[i] <= hi2);
                m |= ((unsigned)in) << i;
            }
        }
        unsigned bl0 = __ballot_sync(0xffffffffu,  m       & 1u);
        unsigned bl1 = __ballot_sync(0xffffffffu, (m >> 1) & 1u);
        unsigned bl2 = __ballot_sync(0xffffffffu, (m >> 2) & 1u);
        unsigned bl3 = __ballot_sync(0xffffffffu, (m >> 3) & 1u);
        if (lane == 0)
            warp_cnt[buf][wid] = __popc(bl0) + __popc(bl1) + __popc(bl2) + __popc(bl3);
        int excl = __popc(bl0 & ltm) + __popc(bl1 & ltm) +
                   __popc(bl2 & ltm) + __popc(bl3 & ltm);
        __syncthreads();

        // shfl-based prefix over 16 warp counts (redundant per warp)
        int v = (lane < 16) ? warp_cnt[buf][lane] : 0;
#pragma unroll
        for (int off = 1; off < 16; off <<= 1) {
            int t = __shfl_up_sync(0xffffffffu, v, off);
            if (lane >= off) v += t;
        }
        int tot = __shfl_sync(0xffffffffu, v, 15);
        int wsrc = (wid == 0) ? 0 : (wid - 1);
        int wofft = __shfl_sync(0xffffffffu, v, wsrc);
        int woff = (wid == 0) ? 0 : wofft;

        int r = run + woff + excl;
#pragma unroll
        for (int i = 0; i < 4; i++) {
            if ((m >> i) & 1u) {
                if (r < NPTS) { s0[r] = v0[i]; s1[r] = v1[i]; s2[r] = v2[i]; }
                r++;
            }
        }
        run += tot;
        buf ^= 1;
        if (run >= NPTS) break;     // uniform (run identical across CTA)
    }
    __syncthreads();

    int n = run;
    if (tid < 300) {
        int axis = tid / 100, pos = tid - axis * 100;
        float v = 0.0f;
        if (n > 0) {
            int j = (n >= NPTS) ? pos : (pos % n);
            v = (axis == 0) ? s0[j] : ((axis == 1) ? s1[j] : s2[j]);
        }
        g_phi[(size_t)b * 300 + tid] = v;
    }
}

// ------------------------------ fused MLP -----------------------------------
// One kernel, BM=32 rows, 512 threads, grid B/32 = 128 (1 CTA/SM, 16 warps).
// Phase 1: h (transposed, in smem hA[c*36+r]) =
//          relu(phi @ W1^T + b1) for c<128 (thread tile 8r x 1c),
//          relu(l @ W2^T + b2)  for c>=128 (per-thread direct).
// Phase 2: out = relu(hA^T @ Wc^T + b34) (thread tile 8r x 2c),
//          Wct double-buffered through the aliased pool.
// Smem pool (floats): phase1 phiAs(9600)+w1Bs(2x2560)+ls(96)=14816
//                     phase2 wctBs(2x4096)=8192 (alias)  ; hA 256*36=9216
#define HA_S   36
#define POOL_F 14816
#define MLP_SMEM_FLOATS (POOL_F + 256 * HA_S)

extern __shared__ float sm[];

__global__ void __launch_bounds__(512, 1) mlp_kernel(
        const float* __restrict__ lt, const float* __restrict__ b1,
        const float* __restrict__ W2, const float* __restrict__ b2,
        float* __restrict__ out) {
    float* phiAs = sm;                 // [k*32 + r], k < 300
    float* w1Bs  = sm + 9600;          // [buf][20*128]
    float* ls    = sm + 14720;         // [96]
    float* hA    = sm + POOL_F;        // [c*36 + r]
    float* wctBs = sm;                 // [buf][16*256] (alias after sync)

    int row0 = blockIdx.x * 32;
    int tid = threadIdx.x;
    int rbase = (tid >> 7) * 8;        // 4 row groups of 8 (warp-uniform)
    int c0 = tid & 127;                // phase-1 column

    // ---- phase 1 staging ----
    // phi transposed, conflict-free STS: r = idx&31 (lane -> distinct row)
    for (int idx = tid; idx < 2400; idx += 512) {
        int r = idx & 31, k4 = idx >> 5;          // k4 in 0..74
        float4 v = *(const float4*)&g_phi[(size_t)(row0 + r) * 300 + k4 * 4];
        phiAs[(k4 * 4 + 0) * 32 + r] = v.x;
        phiAs[(k4 * 4 + 1) * 32 + r] = v.y;
        phiAs[(k4 * 4 + 2) * 32 + r] = v.z;
        phiAs[(k4 * 4 + 3) * 32 + r] = v.w;
    }
    if (tid < 96) ls[tid] = lt[row0 * 3 + tid];
    // W1 tile 0 (640 float4)
#pragma unroll
    for (int j = 0; j < 2; j++) {
        int idx = tid + j * 512;
        if (idx < 640) *(float4*)&w1Bs[idx * 4] = *(const float4*)&g_W1t[idx * 4];
    }

    ull acc[4];
    {
        ull bi = dup2(b1[c0]);
#pragma unroll
        for (int p = 0; p < 4; p++) acc[p] = bi;
    }

    // ---- phase 1 mainloop: 15 K-tiles of 20 ----
    for (int kt = 0; kt < 15; kt++) {
        __syncthreads();
        float4 pw[2];
        bool pv[2] = {false, false};
        if (kt + 1 < 15) {
            const float* src = g_W1t + (kt + 1) * 2560;
#pragma unroll
            for (int j = 0; j < 2; j++) {
                int idx = tid + j * 512;
                if (idx < 640) { pw[j] = *(const float4*)(src + idx * 4); pv[j] = true; }
            }
        }
        const float* Bc = w1Bs + (kt & 1) * 2560;
        int k0 = kt * 20;
#pragma unroll
        for (int kk = 0; kk < 20; kk++) {
            int k = k0 + kk;
            F4U2 a0, a1;
            a0.f4 = *(const float4*)&phiAs[k * 32 + rbase];      // broadcast
            a1.f4 = *(const float4*)&phiAs[k * 32 + rbase + 4];
            ull d = dup2(Bc[kk * 128 + c0]);
            ffma2(acc[0], a0.u2[0], d);
            ffma2(acc[1], a0.u2[1], d);
            ffma2(acc[2], a1.u2[0], d);
            ffma2(acc[3], a1.u2[1], d);
        }
        if (kt + 1 < 15) {
            float* dst = w1Bs + ((kt + 1) & 1) * 2560;
#pragma unroll
            for (int j = 0; j < 2; j++) {
                int idx = tid + j * 512;
                if (pv[j]) *(float4*)(dst + idx * 4) = pw[j];
            }
        }
    }

    // ---- phase 1 epilogue: h^T into hA (one-time STS, conflicts OK) ----
#pragma unroll
    for (int p = 0; p < 4; p++) {
        float2 v = unpack2(acc[p]);
        *(float2*)&hA[c0 * HA_S + rbase + 2 * p] =
            make_float2(fmaxf(v.x, 0.f), fmaxf(v.y, 0.f));
    }
    {   // l_out: col 128+(tid&127), 8 rows (row group tid>>7)
        int c = tid & 127, rh = (tid >> 7) * 8;
        float w0 = W2[c * 3 + 0], w1 = W2[c * 3 + 1], w2 = W2[c * 3 + 2];
        float bc = b2[c];
#pragma unroll
        for (int r = 0; r < 8; r++) {
            float v = bc + ls[(rh + r) * 3 + 0] * w0 + ls[(rh + r) * 3 + 1] * w1
                         + ls[(rh + r) * 3 + 2] * w2;
            hA[(128 + c) * HA_S + rh + r] = fmaxf(v, 0.f);
        }
    }
    __syncthreads();   // pool reads done + hA complete -> safe to alias pool

    // ---- phase 2 staging: Wct tile 0 (1024 float4, 2 per thread) ----
#pragma unroll
    for (int j = 0; j < 2; j++) {
        int idx = tid + j * 512;
        *(float4*)&wctBs[idx * 4] = *(const float4*)&g_Wct[idx * 4];
    }

    int c2 = (tid & 127) * 2;          // phase-2 column pair
    ull acc2[4][2];
#pragma unroll
    for (int p = 0; p < 4; p++) {
        acc2[p][0] = dup2(g_b34[c2]);
        acc2[p][1] = dup2(g_b34[c2 + 1]);
    }

    // ---- phase 2 mainloop: 16 K-tiles of 16 ----
    for (int kt = 0; kt < 16; kt++) {
        __syncthreads();
        float4 pw[2];
        if (kt + 1 < 16) {
            const float* src = g_Wct + (kt + 1) * 4096;
#pragma unroll
            for (int j = 0; j < 2; j++) pw[j] = *(const float4*)(src + (tid + j * 512) * 4);
        }
        const float* Bc = wctBs + (kt & 1) * 4096;
        int k0 = kt * 16;
#pragma unroll
        for (int kk = 0; kk < 16; kk++) {
            int k = k0 + kk;
            F4U2 a0, a1;
            a0.f4 = *(const float4*)&hA[k * HA_S + rbase];       // broadcast, aligned
            a1.f4 = *(const float4*)&hA[k * HA_S + rbase + 4];
            float2 w = *(const float2*)&Bc[kk * 256 + c2];
            ull d0 = dup2(w.x), d1 = dup2(w.y);
            ffma2(acc2[0][0], a0.u2[0], d0); ffma2(acc2[0][1], a0.u2[0], d1);
            ffma2(acc2[1][0], a0.u2[1], d0); ffma2(acc2[1][1], a0.u2[1], d1);
            ffma2(acc2[2][0], a1.u2[0], d0); ffma2(acc2[2][1], a1.u2[0], d1);
            ffma2(acc2[3][0], a1.u2[1], d0); ffma2(acc2[3][1], a1.u2[1], d1);
        }
        if (kt + 1 < 16) {
            float* dst = wctBs + ((kt + 1) & 1) * 4096;
#pragma unroll
            for (int j = 0; j < 2; j++) *(float4*)(dst + (tid + j * 512) * 4) = pw[j];
        }
    }

    // ---- phase 2 epilogue: relu + coalesced float2 stores ----
#pragma unroll
    for (int p = 0; p < 4; p++) {
        float2 v0 = unpack2(acc2[p][0]);   // col c2,   rows 2p/2p+1
        float2 v1 = unpack2(acc2[p][1]);   // col c2+1, rows 2p/2p+1
        size_t base = (size_t)(row0 + rbase + 2 * p) * 256 + c2;
        *(float2*)&out[base]       = make_float2(fmaxf(v0.x, 0.f), fmaxf(v1.x, 0.f));
        *(float2*)&out[base + 256] = make_float2(fmaxf(v0.y, 0.f), fmaxf(v1.y, 0.f));
    }
}

// ------------------------------ launch --------------------------------------
extern "C" void kernel_launch(void* const* d_in, const int* in_sizes, int n_in,
                              void* d_out, int out_size) {
    const float* x  = (const float*)d_in[0];
    const float* lt = (const float*)d_in[1];
    const float* W1 = (const float*)d_in[2];
    const float* b1 = (const float*)d_in[3];
    const float* W2 = (const float*)d_in[4];
    const float* b2 = (const float*)d_in[5];
    const float* W3 = (const float*)d_in[6];
    const float* b3 = (const float*)d_in[7];
    const float* W4 = (const float*)d_in[8];
    const float* b4 = (const float*)d_in[9];
    float* out = (float*)d_out;

    int B = in_sizes[0] / (3 * P_PTS);
    if (B > MAXB) B = MAXB;

    cudaFuncSetAttribute(mlp_kernel, cudaFuncAttributeMaxDynamicSharedMemorySize,
                         MLP_SMEM_FLOATS * sizeof(float));

    foveate_kernel<<<B, 512>>>(x, lt, W1, W3, W4, b3, b4);
    mlp_kernel<<<B / 32, 512, MLP_SMEM_FLOATS * sizeof(float)>>>(lt, b1, W2, b2, out);
}